// round 13
// baseline (speedup 1.0000x reference)
#include <cuda_runtime.h>
#include <cuda_fp16.h>
#include <cstdint>

#define NROWS 8192
#define NSPIN 1024
#define NHID  1024
#define MT    128
#define NT    256
#define NT2   512

// ------------------------ scratch (device globals) ------------------------
__device__ __half g_xhi[(size_t)NROWS * NSPIN];
__device__ __half g_xlo[(size_t)NROWS * NSPIN];
__device__ __half g_wihi[(size_t)NHID * NSPIN];
__device__ __half g_wilo[(size_t)NHID * NSPIN];
__device__ __half g_wqhi[(size_t)NHID * NHID];
__device__ __half g_wqlo[(size_t)NHID * NHID];
__device__ __half g_wkhi[(size_t)NHID * NHID];
__device__ __half g_wklo[(size_t)NHID * NHID];
__device__ __half g_wvhi[(size_t)NHID * NHID];
__device__ __half g_wvlo[(size_t)NHID * NHID];
__device__ __half g_hhi[(size_t)NROWS * NHID];
__device__ __half g_hlo[(size_t)NROWS * NHID];
__device__ __half g_qhi[(size_t)NROWS * NHID];
__device__ __half g_qlo[(size_t)NROWS * NHID];
__device__ __half g_khi[(size_t)NROWS * NHID];
__device__ __half g_klo[(size_t)NROWS * NHID];
__device__ float  g_v  [(size_t)NROWS * NHID];
__device__ __half g_vth[(size_t)NHID * NROWS];   // (v * 4096/c)^T
__device__ __half g_eh [(size_t)NROWS * NROWS];  // E_partial -> E' (in place)
__device__ float  g_cm [NROWS];
__device__ float  g_pt [(size_t)64 * NROWS];     // block maxes -> block sums
__device__ float  g_ic [NROWS];

#define LN2F  0.69314718055994531f
#define L2EF  1.4426950408889634f

// epilogue modes
#define EPI_F32    0
#define EPI_SPLIT  1
#define EPI_EXPMAX 2   // eh = fp16 exp(s - blockmax); pmax = block maxes
#define EPI_LOGC   3

#define SM103A_PATH (defined(__CUDA_ARCH__) && defined(__CUDA_ARCH_FEAT_SM103_ALL))

#if SM103A_PATH
__device__ __forceinline__ uint32_t smem_u32(const void* p) {
    uint32_t a;
    asm("{ .reg .u64 t; cvta.to.shared.u64 t, %1; cvt.u32.u64 %0, t; }"
        : "=r"(a) : "l"(p));
    return a;
}
__device__ __forceinline__ uint32_t elect_one() {
    uint32_t p;
    asm volatile("{\n\t.reg .pred p;\n\telect.sync _|p, 0xFFFFFFFF;\n\t"
                 "selp.b32 %0, 1, 0, p;\n\t}" : "=r"(p));
    return p;
}
__device__ __forceinline__ uint32_t swz128(uint32_t off) {
    return off ^ ((off >> 3) & 0x70);
}
__device__ __forceinline__ void mma_f16_cg2(uint32_t d, uint64_t a, uint64_t b,
                                            uint32_t idesc, uint32_t en) {
    asm volatile("{\n\t.reg .pred p;\n\tsetp.ne.u32 p, %4, 0;\n\t"
                 "tcgen05.mma.cta_group::2.kind::f16 [%0], %1, %2, %3, p;\n\t}"
                 :: "r"(d), "l"(a), "l"(b), "r"(idesc), "r"(en) : "memory");
}
__device__ __forceinline__ void cpa16(uint32_t dst, const void* src) {
    asm volatile("cp.async.cg.shared.global [%0], [%1], 16;"
                 :: "r"(dst), "l"(src) : "memory");
}
#define CP_COMMIT() asm volatile("cp.async.commit_group;" ::: "memory")
#define CP_WAIT1()  asm volatile("cp.async.wait_group 1;" ::: "memory")
#define CP_WAIT2()  asm volatile("cp.async.wait_group 2;" ::: "memory")
#define TC_ALLOC_CG2(sa, n) \
    asm volatile("tcgen05.alloc.cta_group::2.sync.aligned.shared::cta.b32 [%0], %1;" \
                 :: "r"(sa), "r"(n) : "memory")
#define TC_RELINQ_CG2() \
    asm volatile("tcgen05.relinquish_alloc_permit.cta_group::2.sync.aligned;")
#define TC_DEALLOC_CG2(t, n) \
    asm volatile("tcgen05.dealloc.cta_group::2.sync.aligned.b32 %0, %1;" :: "r"(t), "r"(n))
#define TC_COMMIT_MC_CG2(mb) \
    asm volatile("tcgen05.commit.cta_group::2.mbarrier::arrive::one.shared::cluster.multicast::cluster.b64 [%0], %1;" \
                 :: "r"(mb), "h"((uint16_t)0x3) : "memory")
#define TC_FENCE_AFTER()  asm volatile("tcgen05.fence::after_thread_sync;" ::: "memory")
#define TC_WAIT_LD()      asm volatile("tcgen05.wait::ld.sync.aligned;" ::: "memory")
#define FENCE_ASYNC()     asm volatile("fence.proxy.async.shared::cta;" ::: "memory")
#define MBAR_INIT(mb, c) \
    asm volatile("mbarrier.init.shared.b64 [%0], %1;" :: "r"(mb), "r"(c) : "memory")
#define MBAR_ARRIVE(mb) \
    asm volatile("mbarrier.arrive.shared.b64 _, [%0];" :: "r"(mb) : "memory")
#define MBAR_ARRIVE_REMOTE(mb, rk) \
    asm volatile("{\n\t.reg .b32 ra;\n\tmapa.shared::cluster.u32 ra, %0, %1;\n\t" \
                 "mbarrier.arrive.shared::cluster.b64 _, [ra];\n\t}" \
                 :: "r"(mb), "r"(rk) : "memory")
#define MBAR_WAIT(mb, par) do {                                                  \
    asm volatile("{\n\t.reg .pred P1;\n\t"                                       \
                 "WAIT_LOOP_%=:\n\t"                                             \
                 "mbarrier.try_wait.parity.acquire.cta.shared::cta.b64 P1, [%0], %1, 0x989680;\n\t" \
                 "@P1 bra.uni WAIT_DONE_%=;\n\t"                                 \
                 "bra.uni WAIT_LOOP_%=;\n\t"                                     \
                 "WAIT_DONE_%=:\n\t}"                                            \
                 :: "r"(mb), "r"(par) : "memory");                               \
} while (0)
#define MBAR_WAIT_CL(mb, par) do {                                               \
    asm volatile("{\n\t.reg .pred P1;\n\t"                                       \
                 "WAIT_LOOP_%=:\n\t"                                             \
                 "mbarrier.try_wait.parity.acquire.cluster.shared::cta.b64 P1, [%0], %1, 0x989680;\n\t" \
                 "@P1 bra.uni WAIT_DONE_%=;\n\t"                                 \
                 "bra.uni WAIT_LOOP_%=;\n\t"                                     \
                 "WAIT_DONE_%=:\n\t}"                                            \
                 :: "r"(mb), "r"(par) : "memory");                               \
} while (0)
#define CLUSTER_SYNC() do { \
    asm volatile("barrier.cluster.arrive.aligned;" ::: "memory"); \
    asm volatile("barrier.cluster.wait.aligned;" ::: "memory"); \
} while (0)

__device__ __forceinline__ void ldtm32(uint32_t* r, uint32_t addr) {
    asm volatile(
        "tcgen05.ld.sync.aligned.32x32b.x32.b32 "
        "{%0, %1, %2, %3, %4, %5, %6, %7, "
        " %8, %9, %10, %11, %12, %13, %14, %15, "
        " %16, %17, %18, %19, %20, %21, %22, %23, "
        " %24, %25, %26, %27, %28, %29, %30, %31}, [%32];"
        : "=r"(r[0]),  "=r"(r[1]),  "=r"(r[2]),  "=r"(r[3]),
          "=r"(r[4]),  "=r"(r[5]),  "=r"(r[6]),  "=r"(r[7]),
          "=r"(r[8]),  "=r"(r[9]),  "=r"(r[10]), "=r"(r[11]),
          "=r"(r[12]), "=r"(r[13]), "=r"(r[14]), "=r"(r[15]),
          "=r"(r[16]), "=r"(r[17]), "=r"(r[18]), "=r"(r[19]),
          "=r"(r[20]), "=r"(r[21]), "=r"(r[22]), "=r"(r[23]),
          "=r"(r[24]), "=r"(r[25]), "=r"(r[26]), "=r"(r[27]),
          "=r"(r[28]), "=r"(r[29]), "=r"(r[30]), "=r"(r[31])
        : "r"(addr));
}
// SMEM descriptor: SW128, Blackwell version=1, LBO=1, SBO=64 (K-major)
__device__ __forceinline__ uint64_t smem_desc(uint32_t addr) {
    return ((uint64_t)2 << 61) | ((uint64_t)1 << 46) | ((uint64_t)64 << 32) |
           ((uint64_t)1 << 16) | ((uint64_t)(addr >> 4) & 0x3FFF);
}
#define IDESC_F16_CG2 ((1u << 4) | (32u << 17) | (16u << 24))
#endif  // SM103A_PATH

// --- 3-term kernel SMEM: 3 x [Ahi|Alo|Bhi|Blo] 16K each ---
#define SM_TMEMP  0
#define SM_CMT    16
#define SM_RDY    48
#define SM_TILES  1024
#define TILEB     16384
#define BUFB      (4 * TILEB)                // 65536
#define GSMEM     (SM_TILES + 3 * BUFB)      // 197632
// --- 1-term N=512 kernel SMEM: 4 x [A 16K | B 32K] ---
#define BUFB2     (3 * TILEB)
#define GSMEM2    (SM_TILES + 4 * BUFB2)     // 197632

// ==========================================================================
// fp16 GEMM on cg2 MMA (N=256 tile, 3-stage): R = alpha * A @ B^T (+bias)
// ==========================================================================
template <int EPI>
__global__ void __launch_bounds__(256, 1) __cluster_dims__(2, 1, 1)
gemm_h(const __half* __restrict__ Ahi, const __half* __restrict__ Alo,
       const __half* __restrict__ Bhi, const __half* __restrict__ Blo,
       const float* __restrict__ bias, float* __restrict__ C,
       __half* __restrict__ Chi, __half* __restrict__ Clo,
       float* __restrict__ pmax, float* __restrict__ rowout,
       int M, int N, int K, float alpha, int terms) {
#if SM103A_PATH
    extern __shared__ char smem[];
    const uint32_t sb = smem_u32(smem);
    const int tid = threadIdx.x;
    const int wid = tid >> 5;
    const int lid = tid & 31;
    const int ntiles = N / NT;
    const int rank = (int)(blockIdx.x & 1);
    const int pair = (int)(blockIdx.x >> 1);
    const int mtile = pair / ntiles;
    const int ntile = pair % ntiles;
    const int m0 = mtile * 256 + rank * MT;
    const int n0 = ntile * NT;
    const int brow0 = n0 + rank * 128;
    const bool full = (terms == 3);

    if (wid == 0) { TC_ALLOC_CG2(sb + SM_TMEMP, 256); TC_RELINQ_CG2(); }
    if (tid == 0) {
        #pragma unroll
        for (int b = 0; b < 3; b++) {
            MBAR_INIT(sb + SM_CMT + 8 * b, 1);
            MBAR_INIT(sb + SM_RDY + 8 * b, 2);
        }
    }
    __syncthreads();
    CLUSTER_SYNC();

    uint32_t tmem;
    asm volatile("ld.shared.b32 %0, [%1];" : "=r"(tmem) : "r"(sb + SM_TMEMP));

    uint32_t soff[4];
    const __half *pAh[4], *pAl[4], *pBh[4], *pBl[4];
    #pragma unroll
    for (int i = 0; i < 4; i++) {
        int idx = tid + 256 * i, r = idx >> 3, c = idx & 7;
        soff[i] = swz128((uint32_t)(r * 128 + c * 16));
        size_t ga = (size_t)(m0 + r) * K + c * 8;
        size_t gb = (size_t)(brow0 + r) * K + c * 8;
        pAh[i] = Ahi + ga;  pAl[i] = full ? Alo + ga : nullptr;
        pBh[i] = Bhi + gb;  pBl[i] = full ? Blo + gb : nullptr;
    }

    const int nk = K / 64;

    #pragma unroll
    for (int s = 0; s < 2; s++) {
        uint32_t bb = sb + SM_TILES + s * BUFB;
        const int off = s * 64;
        #pragma unroll
        for (int i = 0; i < 4; i++) {
            cpa16(bb + soff[i], pAh[i] + off);
            if (full) cpa16(bb + TILEB + soff[i], pAl[i] + off);
            cpa16(bb + 2 * TILEB + soff[i], pBh[i] + off);
            if (full) cpa16(bb + 3 * TILEB + soff[i], pBl[i] + off);
        }
        CP_COMMIT();
    }

    for (int k0 = 0; k0 < nk; k0++) {
        const int b = k0 % 3;
        CP_WAIT1();
        FENCE_ASYNC();
        __syncthreads();

        if (tid == 0) {
            if (rank == 0) MBAR_ARRIVE(sb + SM_RDY + 8 * b);
            else           MBAR_ARRIVE_REMOTE(sb + SM_RDY + 8 * b, 0);
        }

        if (rank == 0 && wid == 0) {
            if (elect_one()) {
                MBAR_WAIT_CL(sb + SM_RDY + 8 * b, (k0 / 3) & 1);
                uint32_t tb = sb + SM_TILES + b * BUFB;
                uint64_t dAh = smem_desc(tb);
                uint64_t dAl = smem_desc(tb + TILEB);
                uint64_t dBh = smem_desc(tb + 2 * TILEB);
                uint64_t dBl = smem_desc(tb + 3 * TILEB);
                #pragma unroll
                for (int s = 0; s < 4; s++)
                    mma_f16_cg2(tmem, dAh + 2 * s, dBh + 2 * s, IDESC_F16_CG2,
                                (k0 > 0 || s > 0) ? 1u : 0u);
                if (full) {
                    #pragma unroll
                    for (int s = 0; s < 4; s++)
                        mma_f16_cg2(tmem, dAh + 2 * s, dBl + 2 * s, IDESC_F16_CG2, 1u);
                    #pragma unroll
                    for (int s = 0; s < 4; s++)
                        mma_f16_cg2(tmem, dAl + 2 * s, dBh + 2 * s, IDESC_F16_CG2, 1u);
                }
                TC_COMMIT_MC_CG2(sb + SM_CMT + 8 * b);
            }
        }

        if (k0 + 2 < nk) {
            const int b2 = (k0 + 2) % 3;
            if (k0 >= 1)
                MBAR_WAIT(sb + SM_CMT + 8 * b2, ((k0 - 1) / 3) & 1);
            uint32_t bb = sb + SM_TILES + b2 * BUFB;
            const int off = (k0 + 2) * 64;
            #pragma unroll
            for (int i = 0; i < 4; i++) {
                cpa16(bb + soff[i], pAh[i] + off);
                if (full) cpa16(bb + TILEB + soff[i], pAl[i] + off);
                cpa16(bb + 2 * TILEB + soff[i], pBh[i] + off);
                if (full) cpa16(bb + 3 * TILEB + soff[i], pBl[i] + off);
            }
        }
        CP_COMMIT();
    }

    MBAR_WAIT(sb + SM_CMT + 8 * ((nk - 1) % 3), ((nk - 1) / 3) & 1);
    TC_FENCE_AFTER();

    float* wm = (float*)(smem + SM_TILES) + wid * NT;     // warp maxes
    float* bm = (float*)(smem + SM_TILES) + 4 * NT;       // block maxes

    if constexpr (EPI == EPI_EXPMAX) {
        // pass 1: per-warp column maxes across this CTA's 128 rows
        if (wid < 4) {
            #pragma unroll
            for (int g = 0; g < 8; g++) {
                uint32_t d[32];
                ldtm32(d, tmem + g * 32);
                TC_WAIT_LD();
                #pragma unroll
                for (int j = 0; j < 32; j++) {
                    float m = __uint_as_float(d[j]) * alpha;
                    #pragma unroll
                    for (int o = 16; o > 0; o >>= 1)
                        m = fmaxf(m, __shfl_xor_sync(0xffffffffu, m, o));
                    if (lid == j) wm[g * 32 + j] = m;
                }
            }
        }
        __syncthreads();
        if (tid < NT) {
            float m = fmaxf(fmaxf(wm[tid - wid * NT + 0 * NT], 0.f), 0.f);
            // recompute cleanly (wm aliasing above is warp-relative); use flat view:
            const float* w0 = (const float*)(smem + SM_TILES);
            m = fmaxf(fmaxf(w0[tid], w0[NT + tid]),
                      fmaxf(w0[2 * NT + tid], w0[3 * NT + tid]));
            bm[tid] = m;
            pmax[(size_t)(m0 >> 7) * N + n0 + tid] = m;
        }
        __syncthreads();
        // pass 2: re-read TMEM, write fp16 exp(s - blockmax)
        if (wid < 4) {
            const int r = m0 + wid * 32 + lid;
            #pragma unroll
            for (int g = 0; g < 8; g++) {
                uint32_t d[32];
                ldtm32(d, tmem + g * 32);
                TC_WAIT_LD();
                __half* hrow = Chi + (size_t)r * N + n0 + g * 32;
                #pragma unroll
                for (int j = 0; j < 32; j += 2) {
                    float v0 = __uint_as_float(d[j])     * alpha - bm[g * 32 + j];
                    float v1 = __uint_as_float(d[j + 1]) * alpha - bm[g * 32 + j + 1];
                    __half2 e = h2exp2(__floats2half2_rn(v0 * L2EF, v1 * L2EF));
                    *(__half2*)(hrow + j) = e;
                }
            }
        }
    } else if (wid < 4) {
        const int r = m0 + wid * 32 + lid;
        #pragma unroll
        for (int g = 0; g < 8; g++) {
            uint32_t d[32];
            ldtm32(d, tmem + g * 32);
            TC_WAIT_LD();
            const int c0 = n0 + g * 32;
            float vals[32];
            #pragma unroll
            for (int j = 0; j < 32; j++) {
                float v = __uint_as_float(d[j]) * alpha;
                if (EPI == EPI_SPLIT) { if (bias) v += bias[c0 + j]; }
                vals[j] = v;
            }
            if constexpr (EPI == EPI_F32) {
                float* crow = C + (size_t)r * N + c0;
                #pragma unroll
                for (int j = 0; j < 8; j++)
                    *(float4*)(crow + 4 * j) = make_float4(
                        vals[4 * j], vals[4 * j + 1], vals[4 * j + 2], vals[4 * j + 3]);
            }
            if constexpr (EPI == EPI_SPLIT) {
                __half* hrow = Chi + (size_t)r * N + c0;
                __half* lrow = Clo + (size_t)r * N + c0;
                #pragma unroll
                for (int j = 0; j < 16; j++) {
                    float v0 = vals[2 * j], v1 = vals[2 * j + 1];
                    __half h0 = __float2half(v0), h1 = __float2half(v1);
                    __half l0 = __float2half(v0 - __half2float(h0));
                    __half l1 = __float2half(v1 - __half2float(h1));
                    *(__half2*)(hrow + 2 * j) = __halves2half2(h0, h1);
                    *(__half2*)(lrow + 2 * j) = __halves2half2(l0, l1);
                }
            }
        }
    }

    __syncthreads();
    CLUSTER_SYNC();
    if (wid == 0) TC_DEALLOC_CG2(tmem, 256);
    CLUSTER_SYNC();

#else  // fallback (compile-only; never executed)
    const int tid = threadIdx.x;
    const int ntiles = N / NT;
    const int rank = (int)(blockIdx.x & 1);
    const int pair = (int)(blockIdx.x >> 1);
    const int m0 = (pair / ntiles) * 256 + rank * MT;
    const int n0 = (pair % ntiles) * NT;
    if (tid == 0) {
        for (int j = 0; j < NT; j++) {
            int c = n0 + j;
            float vs[128];
            float mx = -3.4e38f;
            for (int rr = 0; rr < 128; rr++) {
                int r = m0 + rr;
                float acc = 0.f;
                for (int kk = 0; kk < K; kk++) {
                    float a = __half2float(Ahi[(size_t)r * K + kk]) +
                              (terms == 3 ? __half2float(Alo[(size_t)r * K + kk]) : 0.f);
                    float b = __half2float(Bhi[(size_t)c * K + kk]) +
                              (terms == 3 ? __half2float(Blo[(size_t)c * K + kk]) : 0.f);
                    acc += a * b;
                }
                float v = acc * alpha + (bias ? bias[c] : 0.f);
                vs[rr] = v;
                mx = fmaxf(mx, v);
                if constexpr (EPI == EPI_F32) C[(size_t)r * N + c] = v;
                if constexpr (EPI == EPI_SPLIT) {
                    __half h = __float2half(v);
                    Chi[(size_t)r * N + c] = h;
                    Clo[(size_t)r * N + c] = __float2half(v - __half2float(h));
                }
            }
            if constexpr (EPI == EPI_EXPMAX) {
                pmax[(size_t)(m0 >> 7) * N + c] = mx;
                for (int rr = 0; rr < 128; rr++)
                    Chi[(size_t)(m0 + rr) * N + c] = __float2half(exp2f((vs[rr] - mx) * L2EF));
            }
        }
    }
#endif
}

// ==========================================================================
// 1-term fp16 GEMM on cg2 MMA, N=512 tile, 4-stage pipeline.
// ==========================================================================
template <int EPI>
__global__ void __launch_bounds__(256, 1) __cluster_dims__(2, 1, 1)
gemm512(const __half* __restrict__ A, const __half* __restrict__ B,
        float* __restrict__ C, float* __restrict__ rowout,
        int M, int N, int K, float alpha) {
#if SM103A_PATH
    extern __shared__ char smem[];
    const uint32_t sb = smem_u32(smem);
    const int tid = threadIdx.x;
    const int wid = tid >> 5;
    const int lid = tid & 31;
    const int ntiles = N / NT2;
    const int rank = (int)(blockIdx.x & 1);
    const int pair = (int)(blockIdx.x >> 1);
    const int mtile = pair / ntiles;
    const int ntile = pair % ntiles;
    const int m0 = mtile * 256 + rank * MT;
    const int n0 = ntile * NT2;

    if (wid == 0) { TC_ALLOC_CG2(sb + SM_TMEMP, 512); TC_RELINQ_CG2(); }
    if (tid == 0) {
        #pragma unroll
        for (int b = 0; b < 4; b++) {
            MBAR_INIT(sb + SM_CMT + 8 * b, 1);
            MBAR_INIT(sb + SM_RDY + 16 + 8 * b, 2);
        }
    }
    __syncthreads();
    CLUSTER_SYNC();

    uint32_t tmem;
    asm volatile("ld.shared.b32 %0, [%1];" : "=r"(tmem) : "r"(sb + SM_TMEMP));

    uint32_t soffA[4], soffB[8];
    const __half *pA[4], *pB[8];
    #pragma unroll
    for (int i = 0; i < 4; i++) {
        int idx = tid + 256 * i, r = idx >> 3, c = idx & 7;
        soffA[i] = swz128((uint32_t)(r * 128 + c * 16));
        pA[i] = A + (size_t)(m0 + r) * K + c * 8;
    }
    #pragma unroll
    for (int i = 0; i < 8; i++) {
        int idx = tid + 256 * i, r = idx >> 3, c = idx & 7;
        soffB[i] = swz128((uint32_t)(r * 128 + c * 16));
        int half = r >> 7, within = r & 127;
        int gr = n0 + half * 256 + rank * 128 + within;
        pB[i] = B + (size_t)gr * K + c * 8;
    }

    const int nk = K / 64;

    #pragma unroll
    for (int s = 0; s < 3; s++) {
        uint32_t bb = sb + SM_TILES + s * BUFB2;
        const int off = s * 64;
        #pragma unroll
        for (int i = 0; i < 4; i++) cpa16(bb + soffA[i], pA[i] + off);
        #pragma unroll
        for (int i = 0; i < 8; i++) cpa16(bb + TILEB + soffB[i], pB[i] + off);
        CP_COMMIT();
    }

    for (int k0 = 0; k0 < nk; k0++) {
        const int b = k0 & 3;
        CP_WAIT2();
        FENCE_ASYNC();
        __syncthreads();

        if (tid == 0) {
            if (rank == 0) MBAR_ARRIVE(sb + SM_RDY + 16 + 8 * b);
            else           MBAR_ARRIVE_REMOTE(sb + SM_RDY + 16 + 8 * b, 0);
        }

        if (rank == 0 && wid == 0) {
            if (elect_one()) {
                MBAR_WAIT_CL(sb + SM_RDY + 16 + 8 * b, (k0 >> 2) & 1);
                uint32_t tb = sb + SM_TILES + b * BUFB2;
                uint64_t dA = smem_desc(tb);
                uint64_t dB0 = smem_desc(tb + TILEB);
                uint64_t dB1 = smem_desc(tb + 2 * TILEB);
                #pragma unroll
                for (int s = 0; s < 4; s++)
                    mma_f16_cg2(tmem, dA + 2 * s, dB0 + 2 * s, IDESC_F16_CG2,
                                (k0 > 0 || s > 0) ? 1u : 0u);
                #pragma unroll
                for (int s = 0; s < 4; s++)
                    mma_f16_cg2(tmem + 256, dA + 2 * s, dB1 + 2 * s, IDESC_F16_CG2,
                                (k0 > 0 || s > 0) ? 1u : 0u);
                TC_COMMIT_MC_CG2(sb + SM_CMT + 8 * b);
            }
        }

        if (k0 + 3 < nk) {
            const int b3 = (k0 + 3) & 3;
            if (k0 >= 1)
                MBAR_WAIT(sb + SM_CMT + 8 * b3, ((k0 - 1) >> 2) & 1);
            uint32_t bb = sb + SM_TILES + b3 * BUFB2;
            const int off = (k0 + 3) * 64;
            #pragma unroll
            for (int i = 0; i < 4; i++) cpa16(bb + soffA[i], pA[i] + off);
            #pragma unroll
            for (int i = 0; i < 8; i++) cpa16(bb + TILEB + soffB[i], pB[i] + off);
        }
        CP_COMMIT();
    }

    MBAR_WAIT(sb + SM_CMT + 8 * ((nk - 1) & 3), ((nk - 1) >> 2) & 1);
    TC_FENCE_AFTER();

    if (wid < 4) {
        const int r = m0 + wid * 32 + lid;
        float lacc = 0.f;
        #pragma unroll
        for (int g = 0; g < 16; g++) {
            uint32_t d[32];
            ldtm32(d, tmem + g * 32);
            TC_WAIT_LD();
            const int c0 = n0 + g * 32;
            float vals[32];
            #pragma unroll
            for (int j = 0; j < 32; j++)
                vals[j] = __uint_as_float(d[j]) * alpha;
            if constexpr (EPI == EPI_F32) {
                float* crow = C + (size_t)r * N + c0;
                #pragma unroll
                for (int j = 0; j < 8; j++)
                    *(float4*)(crow + 4 * j) = make_float4(
                        vals[4 * j], vals[4 * j + 1], vals[4 * j + 2], vals[4 * j + 3]);
            }
            if constexpr (EPI == EPI_LOGC) {
                #pragma unroll
                for (int j = 0; j < 32; j += 2) {
                    float a0 = fabsf(vals[j]), a1 = fabsf(vals[j + 1]);
                    __half2 w = h2exp2(__floats2half2_rn(a0 * (-2.f * L2EF),
                                                         a1 * (-2.f * L2EF)));
                    float2 f = __half22float2(w);
                    lacc += a0 + a1 +
                            LN2F * (__log2f(1.f + f.x) + __log2f(1.f + f.y));
                }
            }
        }
        if constexpr (EPI == EPI_LOGC)
            atomicAdd(rowout + r, lacc - (float)NT2 * LN2F);
    }

    __syncthreads();
    CLUSTER_SYNC();
    if (wid == 0) TC_DEALLOC_CG2(tmem, 512);
    CLUSTER_SYNC();

#else  // fallback (compile-only)
    const int tid = threadIdx.x;
    const int ntiles = N / NT2;
    const int rank = (int)(blockIdx.x & 1);
    const int pair = (int)(blockIdx.x >> 1);
    const int m0 = (pair / ntiles) * 256 + rank * MT;
    const int n0 = (pair % ntiles) * NT2;
    if (tid < 128) {
        int r = m0 + tid;
        float lacc = 0.f;
        for (int j = 0; j < NT2; j++) {
            int c = n0 + j;
            float acc = 0.f;
            for (int kk = 0; kk < K; kk++)
                acc += __half2float(A[(size_t)r * K + kk]) *
                       __half2float(B[(size_t)c * K + kk]);
            float v = acc * alpha;
            if constexpr (EPI == EPI_F32) C[(size_t)r * N + c] = v;
            if constexpr (EPI == EPI_LOGC) {
                float a = fabsf(v);
                lacc += a + log1pf(expf(-2.f * a));
            }
        }
        if constexpr (EPI == EPI_LOGC)
            atomicAdd(rowout + r, lacc - (float)NT2 * LN2F);
    }
#endif
}

// ==========================================================================
__global__ void split2h(const float* __restrict__ in, __half* __restrict__ hi,
                        __half* __restrict__ lo) {
    size_t i = ((size_t)blockIdx.x * 256 + threadIdx.x) * 4;
    float4 v = *(const float4*)(in + i);
    __half h0 = __float2half(v.x), h1 = __float2half(v.y);
    __half h2 = __float2half(v.z), h3 = __float2half(v.w);
    *(__half2*)(hi + i)     = __halves2half2(h0, h1);
    *(__half2*)(hi + i + 2) = __halves2half2(h2, h3);
    *(__half2*)(lo + i)     = __halves2half2(__float2half(v.x - __half2float(h0)),
                                             __float2half(v.y - __half2float(h1)));
    *(__half2*)(lo + i + 2) = __halves2half2(__float2half(v.z - __half2float(h2)),
                                             __float2half(v.w - __half2float(h3)));
}

// global max over the 64 block maxes per column
__global__ void colmax_fin(const float* __restrict__ part, float* __restrict__ cm) {
    int j = blockIdx.x * 256 + threadIdx.x;
    float m = -3.402823e38f;
    #pragma unroll
    for (int i = 0; i < 64; i++)
        m = fmaxf(m, part[(size_t)i * NROWS + j]);
    cm[j] = m;
}

// eh *= 4096*exp(lm - gm) in place; block column sums overwrite pt slots
#define ROWS_PER_BLK 128
__global__ void rescale_sum(__half* __restrict__ E, float* __restrict__ pt,
                            const float* __restrict__ cm) {
    int j = blockIdx.x * 256 + threadIdx.x;
    int yb = blockIdx.y;
    float lm = pt[(size_t)yb * NROWS + j];
    float f = 4096.f * exp2f((lm - cm[j]) * L2EF);
    __half* pe = E + (size_t)yb * ROWS_PER_BLK * NROWS + j;
    float c = 0.f;
    #pragma unroll 4
    for (int i = 0; i < ROWS_PER_BLK; i++) {
        float e = __half2float(pe[(size_t)i * NROWS]) * f;
        pe[(size_t)i * NROWS] = __float2half(e);
        c += e;
    }
    pt[(size_t)yb * NROWS + j] = c;
}

__global__ void invsum_fin(const float* __restrict__ part, float* __restrict__ ic) {
    int j = blockIdx.x * 256 + threadIdx.x;
    float c = 0.f;
    #pragma unroll
    for (int i = 0; i < 64; i++)
        c += part[(size_t)i * NROWS + j];
    ic[j] = 1.f / c;
}

// vth[n,k] = fp16( v[k,n] * 4096 * ic[k] )
__global__ void transpose_scale_h(const float* __restrict__ V,
                                  const float* __restrict__ ic,
                                  __half* __restrict__ VT) {
    __shared__ float t[32][33];
    int n = blockIdx.x * 32 + threadIdx.x;
    int k = blockIdx.y * 32 + threadIdx.y;
    #pragma unroll
    for (int i = 0; i < 32; i += 8)
        t[threadIdx.y + i][threadIdx.x] =
            V[(size_t)(k + i) * NHID + n] * (4096.f * ic[k + i]);
    __syncthreads();
    int ko = blockIdx.y * 32 + threadIdx.x;
    int no = blockIdx.x * 32 + threadIdx.y;
    #pragma unroll
    for (int i = 0; i < 32; i += 8)
        VT[(size_t)(no + i) * NROWS + ko] = __float2half(t[threadIdx.x][threadIdx.y + i]);
}

__global__ void zero_out(float* __restrict__ o) {
    o[blockIdx.x * 256 + threadIdx.x] = 0.f;
}

// ==========================================================================
extern "C" void kernel_launch(void* const* d_in, const int* in_sizes, int n_in,
                              void* d_out, int out_size) {
    const float* x   = (const float*)d_in[0];
    const float* Win = (const float*)d_in[1];
    const float* bin = (const float*)d_in[2];
    const float* Wq  = (const float*)d_in[3];
    const float* Wk  = (const float*)d_in[4];
    const float* Wv  = (const float*)d_in[5];
    float* out = (float*)d_out;

    __half *xhi, *xlo, *wihi, *wilo, *wqhi, *wqlo, *wkhi, *wklo, *wvhi, *wvlo;
    __half *hhi, *hlo, *qhi, *qlo, *khi, *klo, *vth, *eh;
    float *v, *cm, *pt, *ic;
    cudaGetSymbolAddress((void**)&xhi,  g_xhi);
    cudaGetSymbolAddress((void**)&xlo,  g_xlo);
    cudaGetSymbolAddress((void**)&wihi, g_wihi);
    cudaGetSymbolAddress((void**)&wilo, g_wilo);
    cudaGetSymbolAddress((void**)&wqhi, g_wqhi);
    cudaGetSymbolAddress((void**)&wqlo, g_wqlo);
    cudaGetSymbolAddress((void**)&wkhi, g_wkhi);
    cudaGetSymbolAddress((void**)&wklo, g_wklo);
    cudaGetSymbolAddress((void**)&wvhi, g_wvhi);
    cudaGetSymbolAddress((void**)&wvlo, g_wvlo);
    cudaGetSymbolAddress((void**)&hhi,  g_hhi);
    cudaGetSymbolAddress((void**)&hlo,  g_hlo);
    cudaGetSymbolAddress((void**)&qhi,  g_qhi);
    cudaGetSymbolAddress((void**)&qlo,  g_qlo);
    cudaGetSymbolAddress((void**)&khi,  g_khi);
    cudaGetSymbolAddress((void**)&klo,  g_klo);
    cudaGetSymbolAddress((void**)&v,    g_v);
    cudaGetSymbolAddress((void**)&vth,  g_vth);
    cudaGetSymbolAddress((void**)&eh,   g_eh);
    cudaGetSymbolAddress((void**)&cm,   g_cm);
    cudaGetSymbolAddress((void**)&pt,   g_pt);
    cudaGetSymbolAddress((void**)&ic,   g_ic);

    cudaFuncSetAttribute(gemm_h<EPI_F32>,    cudaFuncAttributeMaxDynamicSharedMemorySize, GSMEM);
    cudaFuncSetAttribute(gemm_h<EPI_SPLIT>,  cudaFuncAttributeMaxDynamicSharedMemorySize, GSMEM);
    cudaFuncSetAttribute(gemm_h<EPI_EXPMAX>, cudaFuncAttributeMaxDynamicSharedMemorySize, GSMEM);
    cudaFuncSetAttribute(gemm512<EPI_F32>,   cudaFuncAttributeMaxDynamicSharedMemorySize, GSMEM2);
    cudaFuncSetAttribute(gemm512<EPI_LOGC>,  cudaFuncAttributeMaxDynamicSharedMemorySize, GSMEM2);

    dim3 blk(256);
    const int gHid  = 2 * (NROWS / 256) * (NHID / NT);    // 256
    const int gScr  = 2 * (NROWS / 256) * (NROWS / NT);   // 2048
    const int gAtt  = 2 * (NROWS / 256) * (NHID / NT2);   // 128

    // input splits (fp16 hi/lo)
    split2h<<<(NROWS * NSPIN) / 1024, blk>>>(x, xhi, xlo);
    split2h<<<(NHID * NSPIN) / 1024, blk>>>(Win, wihi, wilo);
    split2h<<<(NHID * NHID) / 1024, blk>>>(Wq, wqhi, wqlo);
    split2h<<<(NHID * NHID) / 1024, blk>>>(Wk, wkhi, wklo);
    split2h<<<(NHID * NHID) / 1024, blk>>>(Wv, wvhi, wvlo);
    zero_out<<<NROWS / 256, blk>>>(out);

    // h = x @ Win^T + b  (3-term, fp16 split out)
    gemm_h<EPI_SPLIT><<<gHid, blk, GSMEM>>>(xhi, xlo, wihi, wilo, bin, nullptr,
                                            hhi, hlo, nullptr, nullptr,
                                            NROWS, NHID, NSPIN, 1.f, 3);
    // q = 0.25 * h @ Wq^T ; k = h @ Wk^T  (3-term, fp16 split out)
    gemm_h<EPI_SPLIT><<<gHid, blk, GSMEM>>>(hhi, hlo, wqhi, wqlo, nullptr, nullptr,
                                            qhi, qlo, nullptr, nullptr,
                                            NROWS, NHID, NHID, 0.25f, 3);
    gemm_h<EPI_SPLIT><<<gHid, blk, GSMEM>>>(hhi, hlo, wkhi, wklo, nullptr, nullptr,
                                            khi, klo, nullptr, nullptr,
                                            NROWS, NHID, NHID, 1.f, 3);
    // v = h @ Wv^T  (1-term, N=512, f32 out)
    gemm512<EPI_F32><<<gAtt, blk, GSMEM2>>>(hhi, wvhi, v, nullptr,
                                            NROWS, NHID, NHID, 1.f);
    // scores: eh = exp(s - blockmax) fp16, pt = block maxes (no f32 s!)
    gemm_h<EPI_EXPMAX><<<gScr, blk, GSMEM>>>(qhi, qlo, khi, klo, nullptr, nullptr,
                                             eh, nullptr, pt, nullptr,
                                             NROWS, NROWS, NHID, 1.f, 3);
    // global colmax; rescale eh in place (+ block sums); 1/colsum
    colmax_fin <<<NROWS / 256, blk>>>(pt, cm);
    rescale_sum<<<dim3(NROWS / 256, 64), blk>>>(eh, pt, cm);
    invsum_fin <<<NROWS / 256, blk>>>(pt, ic);
    // vth = fp16((v * 4096/c)^T)
    transpose_scale_h<<<dim3(NHID / 32, NROWS / 32), dim3(32, 8)>>>(v, ic, vth);
    // out += logcosh partials of (1/4096) * E' @ vth^T  (N=512, 4-stage)
    gemm512<EPI_LOGC><<<gAtt, blk, GSMEM2>>>(eh, vth, nullptr, out,
                                             NROWS, NHID, NROWS, 1.f / 4096.f);
}

// round 14
// speedup vs baseline: 1.3955x; 1.3955x over previous
#include <cuda_runtime.h>
#include <cuda_fp16.h>
#include <cstdint>

#define NROWS 8192
#define NSPIN 1024
#define NHID  1024
#define MT    128
#define NT    256
#define NT2   512

// ------------------------ scratch (device globals) ------------------------
__device__ __half g_xhi[(size_t)NROWS * NSPIN];
__device__ __half g_xlo[(size_t)NROWS * NSPIN];
__device__ __half g_wihi[(size_t)NHID * NSPIN];
__device__ __half g_wilo[(size_t)NHID * NSPIN];
__device__ __half g_wqhi[(size_t)NHID * NHID];
__device__ __half g_wqlo[(size_t)NHID * NHID];
__device__ __half g_wkhi[(size_t)NHID * NHID];
__device__ __half g_wklo[(size_t)NHID * NHID];
__device__ __half g_wvhi[(size_t)NHID * NHID];
__device__ __half g_wvlo[(size_t)NHID * NHID];
__device__ __half g_hhi[(size_t)NROWS * NHID];
__device__ __half g_hlo[(size_t)NROWS * NHID];
__device__ __half g_qhi[(size_t)NROWS * NHID];
__device__ __half g_qlo[(size_t)NROWS * NHID];
__device__ __half g_khi[(size_t)NROWS * NHID];
__device__ __half g_klo[(size_t)NROWS * NHID];
__device__ float  g_v  [(size_t)NROWS * NHID];
__device__ __half g_vth[(size_t)NHID * NROWS];   // (v * 4096/c)^T
__device__ __half g_eh [(size_t)NROWS * NROWS];  // E_partial -> E' (in place)
__device__ float  g_cm [NROWS];
__device__ float  g_pt [(size_t)64 * NROWS];     // block maxes -> block sums
__device__ float  g_ic [NROWS];

#define LN2F  0.69314718055994531f
#define L2EF  1.4426950408889634f

// epilogue modes
#define EPI_F32    0
#define EPI_SPLIT  1
#define EPI_EXPMAX 2
#define EPI_LOGC   3

#define SM103A_PATH (defined(__CUDA_ARCH__) && defined(__CUDA_ARCH_FEAT_SM103_ALL))

#if SM103A_PATH
__device__ __forceinline__ uint32_t smem_u32(const void* p) {
    uint32_t a;
    asm("{ .reg .u64 t; cvta.to.shared.u64 t, %1; cvt.u32.u64 %0, t; }"
        : "=r"(a) : "l"(p));
    return a;
}
__device__ __forceinline__ uint32_t elect_one() {
    uint32_t p;
    asm volatile("{\n\t.reg .pred p;\n\telect.sync _|p, 0xFFFFFFFF;\n\t"
                 "selp.b32 %0, 1, 0, p;\n\t}" : "=r"(p));
    return p;
}
__device__ __forceinline__ uint32_t swz128(uint32_t off) {
    return off ^ ((off >> 3) & 0x70);
}
__device__ __forceinline__ void mma_f16_cg2(uint32_t d, uint64_t a, uint64_t b,
                                            uint32_t idesc, uint32_t en) {
    asm volatile("{\n\t.reg .pred p;\n\tsetp.ne.u32 p, %4, 0;\n\t"
                 "tcgen05.mma.cta_group::2.kind::f16 [%0], %1, %2, %3, p;\n\t}"
                 :: "r"(d), "l"(a), "l"(b), "r"(idesc), "r"(en) : "memory");
}
__device__ __forceinline__ void cpa16(uint32_t dst, const void* src) {
    asm volatile("cp.async.cg.shared.global [%0], [%1], 16;"
                 :: "r"(dst), "l"(src) : "memory");
}
#define CP_COMMIT() asm volatile("cp.async.commit_group;" ::: "memory")
#define CP_WAIT1()  asm volatile("cp.async.wait_group 1;" ::: "memory")
#define CP_WAIT2()  asm volatile("cp.async.wait_group 2;" ::: "memory")
#define TC_ALLOC_CG2(sa, n) \
    asm volatile("tcgen05.alloc.cta_group::2.sync.aligned.shared::cta.b32 [%0], %1;" \
                 :: "r"(sa), "r"(n) : "memory")
#define TC_RELINQ_CG2() \
    asm volatile("tcgen05.relinquish_alloc_permit.cta_group::2.sync.aligned;")
#define TC_DEALLOC_CG2(t, n) \
    asm volatile("tcgen05.dealloc.cta_group::2.sync.aligned.b32 %0, %1;" :: "r"(t), "r"(n))
#define TC_COMMIT_MC_CG2(mb) \
    asm volatile("tcgen05.commit.cta_group::2.mbarrier::arrive::one.shared::cluster.multicast::cluster.b64 [%0], %1;" \
                 :: "r"(mb), "h"((uint16_t)0x3) : "memory")
#define TC_FENCE_AFTER()  asm volatile("tcgen05.fence::after_thread_sync;" ::: "memory")
#define TC_WAIT_LD()      asm volatile("tcgen05.wait::ld.sync.aligned;" ::: "memory")
#define FENCE_ASYNC()     asm volatile("fence.proxy.async.shared::cta;" ::: "memory")
#define MBAR_INIT(mb, c) \
    asm volatile("mbarrier.init.shared.b64 [%0], %1;" :: "r"(mb), "r"(c) : "memory")
#define MBAR_ARRIVE(mb) \
    asm volatile("mbarrier.arrive.shared.b64 _, [%0];" :: "r"(mb) : "memory")
#define MBAR_ARRIVE_REMOTE(mb, rk) \
    asm volatile("{\n\t.reg .b32 ra;\n\tmapa.shared::cluster.u32 ra, %0, %1;\n\t" \
                 "mbarrier.arrive.shared::cluster.b64 _, [ra];\n\t}" \
                 :: "r"(mb), "r"(rk) : "memory")
#define MBAR_WAIT(mb, par) do {                                                  \
    asm volatile("{\n\t.reg .pred P1;\n\t"                                       \
                 "WAIT_LOOP_%=:\n\t"                                             \
                 "mbarrier.try_wait.parity.acquire.cta.shared::cta.b64 P1, [%0], %1, 0x989680;\n\t" \
                 "@P1 bra.uni WAIT_DONE_%=;\n\t"                                 \
                 "bra.uni WAIT_LOOP_%=;\n\t"                                     \
                 "WAIT_DONE_%=:\n\t}"                                            \
                 :: "r"(mb), "r"(par) : "memory");                               \
} while (0)
#define MBAR_WAIT_CL(mb, par) do {                                               \
    asm volatile("{\n\t.reg .pred P1;\n\t"                                       \
                 "WAIT_LOOP_%=:\n\t"                                             \
                 "mbarrier.try_wait.parity.acquire.cluster.shared::cta.b64 P1, [%0], %1, 0x989680;\n\t" \
                 "@P1 bra.uni WAIT_DONE_%=;\n\t"                                 \
                 "bra.uni WAIT_LOOP_%=;\n\t"                                     \
                 "WAIT_DONE_%=:\n\t}"                                            \
                 :: "r"(mb), "r"(par) : "memory");                               \
} while (0)
#define CLUSTER_SYNC() do { \
    asm volatile("barrier.cluster.arrive.aligned;" ::: "memory"); \
    asm volatile("barrier.cluster.wait.aligned;" ::: "memory"); \
} while (0)

__device__ __forceinline__ void ldtm32(uint32_t* r, uint32_t addr) {
    asm volatile(
        "tcgen05.ld.sync.aligned.32x32b.x32.b32 "
        "{%0, %1, %2, %3, %4, %5, %6, %7, "
        " %8, %9, %10, %11, %12, %13, %14, %15, "
        " %16, %17, %18, %19, %20, %21, %22, %23, "
        " %24, %25, %26, %27, %28, %29, %30, %31}, [%32];"
        : "=r"(r[0]),  "=r"(r[1]),  "=r"(r[2]),  "=r"(r[3]),
          "=r"(r[4]),  "=r"(r[5]),  "=r"(r[6]),  "=r"(r[7]),
          "=r"(r[8]),  "=r"(r[9]),  "=r"(r[10]), "=r"(r[11]),
          "=r"(r[12]), "=r"(r[13]), "=r"(r[14]), "=r"(r[15]),
          "=r"(r[16]), "=r"(r[17]), "=r"(r[18]), "=r"(r[19]),
          "=r"(r[20]), "=r"(r[21]), "=r"(r[22]), "=r"(r[23]),
          "=r"(r[24]), "=r"(r[25]), "=r"(r[26]), "=r"(r[27]),
          "=r"(r[28]), "=r"(r[29]), "=r"(r[30]), "=r"(r[31])
        : "r"(addr));
}
// SMEM descriptor: SW128, Blackwell version=1, LBO=1, SBO=64 (K-major)
__device__ __forceinline__ uint64_t smem_desc(uint32_t addr) {
    return ((uint64_t)2 << 61) | ((uint64_t)1 << 46) | ((uint64_t)64 << 32) |
           ((uint64_t)1 << 16) | ((uint64_t)(addr >> 4) & 0x3FFF);
}
#define IDESC_F16_CG2 ((1u << 4) | (32u << 17) | (16u << 24))
#endif  // SM103A_PATH

// --- 3-term kernel SMEM: 3 x [Ahi|Alo|Bhi|Blo] 16K each ---
#define SM_TMEMP  0
#define SM_CMT    16
#define SM_RDY    48
#define SM_TILES  1024
#define TILEB     16384
#define BUFB      (4 * TILEB)                // 65536
#define GSMEM     (SM_TILES + 3 * BUFB)      // 197632
// --- 1-term N=512 kernel SMEM: 4 x [A 16K | B 32K] ---
#define BUFB2     (3 * TILEB)
#define GSMEM2    (SM_TILES + 4 * BUFB2)     // 197632
// epilogue staging: val[c*129 + row], c<256, row<128 -> 132096 B (tiles dead)
#define VPITCH    129

// ==========================================================================
// fp16 GEMM on cg2 MMA (N=256 tile, 3-stage): R = alpha * A @ B^T (+bias)
// ==========================================================================
template <int EPI>
__global__ void __launch_bounds__(256, 1) __cluster_dims__(2, 1, 1)
gemm_h(const __half* __restrict__ Ahi, const __half* __restrict__ Alo,
       const __half* __restrict__ Bhi, const __half* __restrict__ Blo,
       const float* __restrict__ bias, float* __restrict__ C,
       __half* __restrict__ Chi, __half* __restrict__ Clo,
       float* __restrict__ pmax, float* __restrict__ rowout,
       int M, int N, int K, float alpha, int terms) {
#if SM103A_PATH
    extern __shared__ char smem[];
    const uint32_t sb = smem_u32(smem);
    const int tid = threadIdx.x;
    const int wid = tid >> 5;
    const int lid = tid & 31;
    const int ntiles = N / NT;
    const int rank = (int)(blockIdx.x & 1);
    const int pair = (int)(blockIdx.x >> 1);
    const int mtile = pair / ntiles;
    const int ntile = pair % ntiles;
    const int m0 = mtile * 256 + rank * MT;
    const int n0 = ntile * NT;
    const int brow0 = n0 + rank * 128;
    const bool full = (terms == 3);

    if (wid == 0) { TC_ALLOC_CG2(sb + SM_TMEMP, 256); TC_RELINQ_CG2(); }
    if (tid == 0) {
        #pragma unroll
        for (int b = 0; b < 3; b++) {
            MBAR_INIT(sb + SM_CMT + 8 * b, 1);
            MBAR_INIT(sb + SM_RDY + 8 * b, 2);
        }
    }
    __syncthreads();
    CLUSTER_SYNC();

    uint32_t tmem;
    asm volatile("ld.shared.b32 %0, [%1];" : "=r"(tmem) : "r"(sb + SM_TMEMP));

    uint32_t soff[4];
    const __half *pAh[4], *pAl[4], *pBh[4], *pBl[4];
    #pragma unroll
    for (int i = 0; i < 4; i++) {
        int idx = tid + 256 * i, r = idx >> 3, c = idx & 7;
        soff[i] = swz128((uint32_t)(r * 128 + c * 16));
        size_t ga = (size_t)(m0 + r) * K + c * 8;
        size_t gb = (size_t)(brow0 + r) * K + c * 8;
        pAh[i] = Ahi + ga;  pAl[i] = full ? Alo + ga : nullptr;
        pBh[i] = Bhi + gb;  pBl[i] = full ? Blo + gb : nullptr;
    }

    const int nk = K / 64;

    #pragma unroll
    for (int s = 0; s < 2; s++) {
        uint32_t bb = sb + SM_TILES + s * BUFB;
        const int off = s * 64;
        #pragma unroll
        for (int i = 0; i < 4; i++) {
            cpa16(bb + soff[i], pAh[i] + off);
            if (full) cpa16(bb + TILEB + soff[i], pAl[i] + off);
            cpa16(bb + 2 * TILEB + soff[i], pBh[i] + off);
            if (full) cpa16(bb + 3 * TILEB + soff[i], pBl[i] + off);
        }
        CP_COMMIT();
    }

    for (int k0 = 0; k0 < nk; k0++) {
        const int b = k0 % 3;
        CP_WAIT1();
        FENCE_ASYNC();
        __syncthreads();

        if (tid == 0) {
            if (rank == 0) MBAR_ARRIVE(sb + SM_RDY + 8 * b);
            else           MBAR_ARRIVE_REMOTE(sb + SM_RDY + 8 * b, 0);
        }

        if (rank == 0 && wid == 0) {
            if (elect_one()) {
                MBAR_WAIT_CL(sb + SM_RDY + 8 * b, (k0 / 3) & 1);
                uint32_t tb = sb + SM_TILES + b * BUFB;
                uint64_t dAh = smem_desc(tb);
                uint64_t dAl = smem_desc(tb + TILEB);
                uint64_t dBh = smem_desc(tb + 2 * TILEB);
                uint64_t dBl = smem_desc(tb + 3 * TILEB);
                #pragma unroll
                for (int s = 0; s < 4; s++)
                    mma_f16_cg2(tmem, dAh + 2 * s, dBh + 2 * s, IDESC_F16_CG2,
                                (k0 > 0 || s > 0) ? 1u : 0u);
                if (full) {
                    #pragma unroll
                    for (int s = 0; s < 4; s++)
                        mma_f16_cg2(tmem, dAh + 2 * s, dBl + 2 * s, IDESC_F16_CG2, 1u);
                    #pragma unroll
                    for (int s = 0; s < 4; s++)
                        mma_f16_cg2(tmem, dAl + 2 * s, dBh + 2 * s, IDESC_F16_CG2, 1u);
                }
                TC_COMMIT_MC_CG2(sb + SM_CMT + 8 * b);
            }
        }

        if (k0 + 2 < nk) {
            const int b2 = (k0 + 2) % 3;
            if (k0 >= 1)
                MBAR_WAIT(sb + SM_CMT + 8 * b2, ((k0 - 1) / 3) & 1);
            uint32_t bb = sb + SM_TILES + b2 * BUFB;
            const int off = (k0 + 2) * 64;
            #pragma unroll
            for (int i = 0; i < 4; i++) {
                cpa16(bb + soff[i], pAh[i] + off);
                if (full) cpa16(bb + TILEB + soff[i], pAl[i] + off);
                cpa16(bb + 2 * TILEB + soff[i], pBh[i] + off);
                if (full) cpa16(bb + 3 * TILEB + soff[i], pBl[i] + off);
            }
        }
        CP_COMMIT();
    }

    MBAR_WAIT(sb + SM_CMT + 8 * ((nk - 1) % 3), ((nk - 1) / 3) & 1);
    TC_FENCE_AFTER();

    float* sv = (float*)(smem + SM_TILES);   // staged vals [c*129 + row]

    if constexpr (EPI == EPI_EXPMAX || EPI == EPI_SPLIT) {
        // phase 1: single TMEM drain -> transposed SMEM staging
        if (wid < 4) {
            const int row = wid * 32 + lid;
            #pragma unroll
            for (int g = 0; g < 8; g++) {
                uint32_t d[32];
                ldtm32(d, tmem + g * 32);
                TC_WAIT_LD();
                #pragma unroll
                for (int j = 0; j < 32; j++)
                    sv[(g * 32 + j) * VPITCH + row] = __uint_as_float(d[j]) * alpha;
            }
        }
        __syncthreads();
        // phase 2: thread-per-column, coalesced global writes
        const int c = tid;            // 0..255
        if constexpr (EPI == EPI_EXPMAX) {
            float m = -3.402823e38f;
            #pragma unroll 4
            for (int i = 0; i < 128; i++)
                m = fmaxf(m, sv[c * VPITCH + i]);
            pmax[(size_t)(m0 >> 7) * N + n0 + c] = m;
            __half* ecol = Chi + (size_t)m0 * N + n0 + c;
            #pragma unroll 4
            for (int i = 0; i < 128; i++) {
                float e = __expf(sv[c * VPITCH + i] - m);
                ecol[(size_t)i * N] = __float2half(e);
            }
        } else {  // EPI_SPLIT
            const float bc = bias ? bias[n0 + c] : 0.f;
            __half* hcol = Chi + (size_t)m0 * N + n0 + c;
            __half* lcol = Clo + (size_t)m0 * N + n0 + c;
            #pragma unroll 4
            for (int i = 0; i < 128; i++) {
                float v = sv[c * VPITCH + i] + bc;
                __half h = __float2half(v);
                hcol[(size_t)i * N] = h;
                lcol[(size_t)i * N] = __float2half(v - __half2float(h));
            }
        }
    } else if (wid < 4) {   // EPI_F32
        const int r = m0 + wid * 32 + lid;
        #pragma unroll
        for (int g = 0; g < 8; g++) {
            uint32_t d[32];
            ldtm32(d, tmem + g * 32);
            TC_WAIT_LD();
            float* crow = C + (size_t)r * N + n0 + g * 32;
            #pragma unroll
            for (int j = 0; j < 8; j++)
                *(float4*)(crow + 4 * j) = make_float4(
                    __uint_as_float(d[4 * j + 0]) * alpha,
                    __uint_as_float(d[4 * j + 1]) * alpha,
                    __uint_as_float(d[4 * j + 2]) * alpha,
                    __uint_as_float(d[4 * j + 3]) * alpha);
        }
    }

    __syncthreads();
    CLUSTER_SYNC();
    if (wid == 0) TC_DEALLOC_CG2(tmem, 256);
    CLUSTER_SYNC();

#else  // fallback (compile-only; never executed)
    const int tid = threadIdx.x;
    const int ntiles = N / NT;
    const int rank = (int)(blockIdx.x & 1);
    const int pair = (int)(blockIdx.x >> 1);
    const int m0 = (pair / ntiles) * 256 + rank * MT;
    const int n0 = (pair % ntiles) * NT;
    if (tid == 0) {
        for (int j = 0; j < NT; j++) {
            int c = n0 + j;
            float vs[128];
            float mx = -3.4e38f;
            for (int rr = 0; rr < 128; rr++) {
                int r = m0 + rr;
                float acc = 0.f;
                for (int kk = 0; kk < K; kk++) {
                    float a = __half2float(Ahi[(size_t)r * K + kk]) +
                              (terms == 3 ? __half2float(Alo[(size_t)r * K + kk]) : 0.f);
                    float b = __half2float(Bhi[(size_t)c * K + kk]) +
                              (terms == 3 ? __half2float(Blo[(size_t)c * K + kk]) : 0.f);
                    acc += a * b;
                }
                float v = acc * alpha + (bias ? bias[c] : 0.f);
                vs[rr] = v;
                mx = fmaxf(mx, v);
                if constexpr (EPI == EPI_F32) C[(size_t)r * N + c] = v;
                if constexpr (EPI == EPI_SPLIT) {
                    __half h = __float2half(v);
                    Chi[(size_t)r * N + c] = h;
                    Clo[(size_t)r * N + c] = __float2half(v - __half2float(h));
                }
            }
            if constexpr (EPI == EPI_EXPMAX) {
                pmax[(size_t)(m0 >> 7) * N + c] = mx;
                for (int rr = 0; rr < 128; rr++)
                    Chi[(size_t)(m0 + rr) * N + c] = __float2half(expf(vs[rr] - mx));
            }
        }
    }
#endif
}

// ==========================================================================
// 1-term fp16 GEMM on cg2 MMA, N=512 tile, 4-stage pipeline.
// ==========================================================================
template <int EPI>
__global__ void __launch_bounds__(256, 1) __cluster_dims__(2, 1, 1)
gemm512(const __half* __restrict__ A, const __half* __restrict__ B,
        float* __restrict__ C, float* __restrict__ rowout,
        int M, int N, int K, float alpha) {
#if SM103A_PATH
    extern __shared__ char smem[];
    const uint32_t sb = smem_u32(smem);
    const int tid = threadIdx.x;
    const int wid = tid >> 5;
    const int lid = tid & 31;
    const int ntiles = N / NT2;
    const int rank = (int)(blockIdx.x & 1);
    const int pair = (int)(blockIdx.x >> 1);
    const int mtile = pair / ntiles;
    const int ntile = pair % ntiles;
    const int m0 = mtile * 256 + rank * MT;
    const int n0 = ntile * NT2;

    if (wid == 0) { TC_ALLOC_CG2(sb + SM_TMEMP, 512); TC_RELINQ_CG2(); }
    if (tid == 0) {
        #pragma unroll
        for (int b = 0; b < 4; b++) {
            MBAR_INIT(sb + SM_CMT + 8 * b, 1);
            MBAR_INIT(sb + SM_RDY + 16 + 8 * b, 2);
        }
    }
    __syncthreads();
    CLUSTER_SYNC();

    uint32_t tmem;
    asm volatile("ld.shared.b32 %0, [%1];" : "=r"(tmem) : "r"(sb + SM_TMEMP));

    uint32_t soffA[4], soffB[8];
    const __half *pA[4], *pB[8];
    #pragma unroll
    for (int i = 0; i < 4; i++) {
        int idx = tid + 256 * i, r = idx >> 3, c = idx & 7;
        soffA[i] = swz128((uint32_t)(r * 128 + c * 16));
        pA[i] = A + (size_t)(m0 + r) * K + c * 8;
    }
    #pragma unroll
    for (int i = 0; i < 8; i++) {
        int idx = tid + 256 * i, r = idx >> 3, c = idx & 7;
        soffB[i] = swz128((uint32_t)(r * 128 + c * 16));
        int half = r >> 7, within = r & 127;
        int gr = n0 + half * 256 + rank * 128 + within;
        pB[i] = B + (size_t)gr * K + c * 8;
    }

    const int nk = K / 64;

    #pragma unroll
    for (int s = 0; s < 3; s++) {
        uint32_t bb = sb + SM_TILES + s * BUFB2;
        const int off = s * 64;
        #pragma unroll
        for (int i = 0; i < 4; i++) cpa16(bb + soffA[i], pA[i] + off);
        #pragma unroll
        for (int i = 0; i < 8; i++) cpa16(bb + TILEB + soffB[i], pB[i] + off);
        CP_COMMIT();
    }

    for (int k0 = 0; k0 < nk; k0++) {
        const int b = k0 & 3;
        CP_WAIT2();
        FENCE_ASYNC();
        __syncthreads();

        if (tid == 0) {
            if (rank == 0) MBAR_ARRIVE(sb + SM_RDY + 16 + 8 * b);
            else           MBAR_ARRIVE_REMOTE(sb + SM_RDY + 16 + 8 * b, 0);
        }

        if (rank == 0 && wid == 0) {
            if (elect_one()) {
                MBAR_WAIT_CL(sb + SM_RDY + 16 + 8 * b, (k0 >> 2) & 1);
                uint32_t tb = sb + SM_TILES + b * BUFB2;
                uint64_t dA = smem_desc(tb);
                uint64_t dB0 = smem_desc(tb + TILEB);
                uint64_t dB1 = smem_desc(tb + 2 * TILEB);
                #pragma unroll
                for (int s = 0; s < 4; s++)
                    mma_f16_cg2(tmem, dA + 2 * s, dB0 + 2 * s, IDESC_F16_CG2,
                                (k0 > 0 || s > 0) ? 1u : 0u);
                #pragma unroll
                for (int s = 0; s < 4; s++)
                    mma_f16_cg2(tmem + 256, dA + 2 * s, dB1 + 2 * s, IDESC_F16_CG2,
                                (k0 > 0 || s > 0) ? 1u : 0u);
                TC_COMMIT_MC_CG2(sb + SM_CMT + 8 * b);
            }
        }

        if (k0 + 3 < nk) {
            const int b3 = (k0 + 3) & 3;
            if (k0 >= 1)
                MBAR_WAIT(sb + SM_CMT + 8 * b3, ((k0 - 1) >> 2) & 1);
            uint32_t bb = sb + SM_TILES + b3 * BUFB2;
            const int off = (k0 + 3) * 64;
            #pragma unroll
            for (int i = 0; i < 4; i++) cpa16(bb + soffA[i], pA[i] + off);
            #pragma unroll
            for (int i = 0; i < 8; i++) cpa16(bb + TILEB + soffB[i], pB[i] + off);
        }
        CP_COMMIT();
    }

    MBAR_WAIT(sb + SM_CMT + 8 * ((nk - 1) & 3), ((nk - 1) >> 2) & 1);
    TC_FENCE_AFTER();

    if (wid < 4) {
        const int r = m0 + wid * 32 + lid;
        float lacc = 0.f;
        #pragma unroll
        for (int g = 0; g < 16; g++) {
            uint32_t d[32];
            ldtm32(d, tmem + g * 32);
            TC_WAIT_LD();
            const int c0 = n0 + g * 32;
            float vals[32];
            #pragma unroll
            for (int j = 0; j < 32; j++)
                vals[j] = __uint_as_float(d[j]) * alpha;
            if constexpr (EPI == EPI_F32) {
                float* crow = C + (size_t)r * N + c0;
                #pragma unroll
                for (int j = 0; j < 8; j++)
                    *(float4*)(crow + 4 * j) = make_float4(
                        vals[4 * j], vals[4 * j + 1], vals[4 * j + 2], vals[4 * j + 3]);
            }
            if constexpr (EPI == EPI_LOGC) {
                #pragma unroll
                for (int j = 0; j < 32; j += 2) {
                    float a0 = fabsf(vals[j]), a1 = fabsf(vals[j + 1]);
                    __half2 w = h2exp2(__floats2half2_rn(a0 * (-2.f * L2EF),
                                                         a1 * (-2.f * L2EF)));
                    float2 f = __half22float2(w);
                    lacc += a0 + a1 +
                            LN2F * (__log2f(1.f + f.x) + __log2f(1.f + f.y));
                }
            }
        }
        if constexpr (EPI == EPI_LOGC)
            atomicAdd(rowout + r, lacc - (float)NT2 * LN2F);
    }

    __syncthreads();
    CLUSTER_SYNC();
    if (wid == 0) TC_DEALLOC_CG2(tmem, 512);
    CLUSTER_SYNC();

#else  // fallback (compile-only)
    const int tid = threadIdx.x;
    const int ntiles = N / NT2;
    const int rank = (int)(blockIdx.x & 1);
    const int pair = (int)(blockIdx.x >> 1);
    const int m0 = (pair / ntiles) * 256 + rank * MT;
    const int n0 = (pair % ntiles) * NT2;
    if (tid < 128) {
        int r = m0 + tid;
        float lacc = 0.f;
        for (int j = 0; j < NT2; j++) {
            int c = n0 + j;
            float acc = 0.f;
            for (int kk = 0; kk < K; kk++)
                acc += __half2float(A[(size_t)r * K + kk]) *
                       __half2float(B[(size_t)c * K + kk]);
            float v = acc * alpha;
            if constexpr (EPI == EPI_F32) C[(size_t)r * N + c] = v;
            if constexpr (EPI == EPI_LOGC) {
                float a = fabsf(v);
                lacc += a + log1pf(expf(-2.f * a));
            }
        }
        if constexpr (EPI == EPI_LOGC)
            atomicAdd(rowout + r, lacc - (float)NT2 * LN2F);
    }
#endif
}

// ==========================================================================
__global__ void split2h(const float* __restrict__ in, __half* __restrict__ hi,
                        __half* __restrict__ lo) {
    size_t i = ((size_t)blockIdx.x * 256 + threadIdx.x) * 4;
    float4 v = *(const float4*)(in + i);
    __half h0 = __float2half(v.x), h1 = __float2half(v.y);
    __half h2 = __float2half(v.z), h3 = __float2half(v.w);
    *(__half2*)(hi + i)     = __halves2half2(h0, h1);
    *(__half2*)(hi + i + 2) = __halves2half2(h2, h3);
    *(__half2*)(lo + i)     = __halves2half2(__float2half(v.x - __half2float(h0)),
                                             __float2half(v.y - __half2float(h1)));
    *(__half2*)(lo + i + 2) = __halves2half2(__float2half(v.z - __half2float(h2)),
                                             __float2half(v.w - __half2float(h3)));
}

// global max over the 64 block maxes per column
__global__ void colmax_fin(const float* __restrict__ part, float* __restrict__ cm) {
    int j = blockIdx.x * 256 + threadIdx.x;
    float m = -3.402823e38f;
    #pragma unroll
    for (int i = 0; i < 64; i++)
        m = fmaxf(m, part[(size_t)i * NROWS + j]);
    cm[j] = m;
}

// eh *= 4096*exp(lm - gm) in place; block column sums overwrite pt slots
#define ROWS_PER_BLK 128
__global__ void rescale_sum(__half* __restrict__ E, float* __restrict__ pt,
                            const float* __restrict__ cm) {
    int j = blockIdx.x * 256 + threadIdx.x;
    int yb = blockIdx.y;
    float lm = pt[(size_t)yb * NROWS + j];
    float f = 4096.f * __expf(lm - cm[j]);
    __half* pe = E + (size_t)yb * ROWS_PER_BLK * NROWS + j;
    float c = 0.f;
    #pragma unroll 4
    for (int i = 0; i < ROWS_PER_BLK; i++) {
        float e = __half2float(pe[(size_t)i * NROWS]) * f;
        pe[(size_t)i * NROWS] = __float2half(e);
        c += e;
    }
    pt[(size_t)yb * NROWS + j] = c;
}

__global__ void invsum_fin(const float* __restrict__ part, float* __restrict__ ic) {
    int j = blockIdx.x * 256 + threadIdx.x;
    float c = 0.f;
    #pragma unroll
    for (int i = 0; i < 64; i++)
        c += part[(size_t)i * NROWS + j];
    ic[j] = 1.f / c;
}

// vth[n,k] = fp16( v[k,n] * 4096 * ic[k] )
__global__ void transpose_scale_h(const float* __restrict__ V,
                                  const float* __restrict__ ic,
                                  __half* __restrict__ VT) {
    __shared__ float t[32][33];
    int n = blockIdx.x * 32 + threadIdx.x;
    int k = blockIdx.y * 32 + threadIdx.y;
    #pragma unroll
    for (int i = 0; i < 32; i += 8)
        t[threadIdx.y + i][threadIdx.x] =
            V[(size_t)(k + i) * NHID + n] * (4096.f * ic[k + i]);
    __syncthreads();
    int ko = blockIdx.y * 32 + threadIdx.x;
    int no = blockIdx.x * 32 + threadIdx.y;
    #pragma unroll
    for (int i = 0; i < 32; i += 8)
        VT[(size_t)(no + i) * NROWS + ko] = __float2half(t[threadIdx.x][threadIdx.y + i]);
}

__global__ void zero_out(float* __restrict__ o) {
    o[blockIdx.x * 256 + threadIdx.x] = 0.f;
}

// ==========================================================================
extern "C" void kernel_launch(void* const* d_in, const int* in_sizes, int n_in,
                              void* d_out, int out_size) {
    const float* x   = (const float*)d_in[0];
    const float* Win = (const float*)d_in[1];
    const float* bin = (const float*)d_in[2];
    const float* Wq  = (const float*)d_in[3];
    const float* Wk  = (const float*)d_in[4];
    const float* Wv  = (const float*)d_in[5];
    float* out = (float*)d_out;

    __half *xhi, *xlo, *wihi, *wilo, *wqhi, *wqlo, *wkhi, *wklo, *wvhi, *wvlo;
    __half *hhi, *hlo, *qhi, *qlo, *khi, *klo, *vth, *eh;
    float *v, *cm, *pt, *ic;
    cudaGetSymbolAddress((void**)&xhi,  g_xhi);
    cudaGetSymbolAddress((void**)&xlo,  g_xlo);
    cudaGetSymbolAddress((void**)&wihi, g_wihi);
    cudaGetSymbolAddress((void**)&wilo, g_wilo);
    cudaGetSymbolAddress((void**)&wqhi, g_wqhi);
    cudaGetSymbolAddress((void**)&wqlo, g_wqlo);
    cudaGetSymbolAddress((void**)&wkhi, g_wkhi);
    cudaGetSymbolAddress((void**)&wklo, g_wklo);
    cudaGetSymbolAddress((void**)&wvhi, g_wvhi);
    cudaGetSymbolAddress((void**)&wvlo, g_wvlo);
    cudaGetSymbolAddress((void**)&hhi,  g_hhi);
    cudaGetSymbolAddress((void**)&hlo,  g_hlo);
    cudaGetSymbolAddress((void**)&qhi,  g_qhi);
    cudaGetSymbolAddress((void**)&qlo,  g_qlo);
    cudaGetSymbolAddress((void**)&khi,  g_khi);
    cudaGetSymbolAddress((void**)&klo,  g_klo);
    cudaGetSymbolAddress((void**)&v,    g_v);
    cudaGetSymbolAddress((void**)&vth,  g_vth);
    cudaGetSymbolAddress((void**)&eh,   g_eh);
    cudaGetSymbolAddress((void**)&cm,   g_cm);
    cudaGetSymbolAddress((void**)&pt,   g_pt);
    cudaGetSymbolAddress((void**)&ic,   g_ic);

    cudaFuncSetAttribute(gemm_h<EPI_F32>,    cudaFuncAttributeMaxDynamicSharedMemorySize, GSMEM);
    cudaFuncSetAttribute(gemm_h<EPI_SPLIT>,  cudaFuncAttributeMaxDynamicSharedMemorySize, GSMEM);
    cudaFuncSetAttribute(gemm_h<EPI_EXPMAX>, cudaFuncAttributeMaxDynamicSharedMemorySize, GSMEM);
    cudaFuncSetAttribute(gemm512<EPI_F32>,   cudaFuncAttributeMaxDynamicSharedMemorySize, GSMEM2);
    cudaFuncSetAttribute(gemm512<EPI_LOGC>,  cudaFuncAttributeMaxDynamicSharedMemorySize, GSMEM2);

    dim3 blk(256);
    const int gHid  = 2 * (NROWS / 256) * (NHID / NT);    // 256
    const int gScr  = 2 * (NROWS / 256) * (NROWS / NT);   // 2048
    const int gAtt  = 2 * (NROWS / 256) * (NHID / NT2);   // 128

    // input splits (fp16 hi/lo)
    split2h<<<(NROWS * NSPIN) / 1024, blk>>>(x, xhi, xlo);
    split2h<<<(NHID * NSPIN) / 1024, blk>>>(Win, wihi, wilo);
    split2h<<<(NHID * NHID) / 1024, blk>>>(Wq, wqhi, wqlo);
    split2h<<<(NHID * NHID) / 1024, blk>>>(Wk, wkhi, wklo);
    split2h<<<(NHID * NHID) / 1024, blk>>>(Wv, wvhi, wvlo);
    zero_out<<<NROWS / 256, blk>>>(out);

    // h = x @ Win^T + b  (3-term, fp16 split out)
    gemm_h<EPI_SPLIT><<<gHid, blk, GSMEM>>>(xhi, xlo, wihi, wilo, bin, nullptr,
                                            hhi, hlo, nullptr, nullptr,
                                            NROWS, NHID, NSPIN, 1.f, 3);
    // q = 0.25 * h @ Wq^T ; k = h @ Wk^T  (3-term, fp16 split out)
    gemm_h<EPI_SPLIT><<<gHid, blk, GSMEM>>>(hhi, hlo, wqhi, wqlo, nullptr, nullptr,
                                            qhi, qlo, nullptr, nullptr,
                                            NROWS, NHID, NHID, 0.25f, 3);
    gemm_h<EPI_SPLIT><<<gHid, blk, GSMEM>>>(hhi, hlo, wkhi, wklo, nullptr, nullptr,
                                            khi, klo, nullptr, nullptr,
                                            NROWS, NHID, NHID, 1.f, 3);
    // v = h @ Wv^T  (1-term, N=512, f32 out)
    gemm512<EPI_F32><<<gAtt, blk, GSMEM2>>>(hhi, wvhi, v, nullptr,
                                            NROWS, NHID, NHID, 1.f);
    // scores: eh = exp(s - blockmax) fp16, pt = block maxes (no f32 s)
    gemm_h<EPI_EXPMAX><<<gScr, blk, GSMEM>>>(qhi, qlo, khi, klo, nullptr, nullptr,
                                             eh, nullptr, pt, nullptr,
                                             NROWS, NROWS, NHID, 1.f, 3);
    // global colmax; rescale eh in place (+ block sums); 1/colsum
    colmax_fin <<<NROWS / 256, blk>>>(pt, cm);
    rescale_sum<<<dim3(NROWS / 256, 64), blk>>>(eh, pt, cm);
    invsum_fin <<<NROWS / 256, blk>>>(pt, ic);
    // vth = fp16((v * 4096/c)^T)
    transpose_scale_h<<<dim3(NHID / 32, NROWS / 32), dim3(32, 8)>>>(v, ic, vth);
    // out += logcosh partials of (1/4096) * E' @ vth^T  (N=512, 4-stage)
    gemm512<EPI_LOGC><<<gAtt, blk, GSMEM2>>>(eh, vth, nullptr, out,
                                             NROWS, NHID, NROWS, 1.f / 4096.f);
}